// round 4
// baseline (speedup 1.0000x reference)
#include <cuda_runtime.h>
#include <math.h>

#define NTOK 32768
#define NM   4
#define IND  204
#define HD   128
#define AD   14
#define KD   32
#define TILE 32
#define FULL 0xffffffffu

typedef unsigned long long u64;

// -------- device scratch (no allocations allowed) --------
__device__ float g_kp[NM * KD];
__device__ int   g_cnt[NM];
__device__ int   g_ticket;
__device__ int   g_idx[NM * NTOK];

__device__ __forceinline__ float sigmf(float v) {
    return 1.0f / (1.0f + __expf(-v));
}

// ---- packed f32x2 helpers (Blackwell FFMA2 path) ----
__device__ __forceinline__ u64 pk2d(float v) {            // duplicate
    u64 r; asm("mov.b64 %0,{%1,%1};" : "=l"(r) : "f"(v)); return r;
}
__device__ __forceinline__ u64 pk2(float a, float b) {
    u64 r; asm("mov.b64 %0,{%1,%2};" : "=l"(r) : "f"(a), "f"(b)); return r;
}
__device__ __forceinline__ void fma2(u64& d, u64 a, u64 b) {
    asm("fma.rn.f32x2 %0,%1,%2,%0;" : "+l"(d) : "l"(a), "l"(b));
}
__device__ __forceinline__ float2 unpk(u64 v) {
    float2 f; asm("mov.b64 {%0,%1},%2;" : "=f"(f.x), "=f"(f.y) : "l"(v)); return f;
}

// ---------------- kernel 0: mechanism keys projection + counter reset ----------------
__global__ void kp_kernel(const float* __restrict__ mech_keys,
                          const float* __restrict__ wk,
                          const float* __restrict__ bk)
{
    int tid = threadIdx.x;
    if (tid == 0) g_ticket = 0;
    if (tid < NM) g_cnt[tid] = 0;
    if (tid < NM * KD) {
        int m = tid >> 5, k = tid & 31;
        float acc = bk[k];
        #pragma unroll
        for (int i = 0; i < KD; i++)
            acc = fmaf(mech_keys[m * KD + i], wk[i * KD + k], acc);
        g_kp[tid] = acc;
    }
}

// ---------------- router: query MLP + attention + gumbel argmax + bucket sort ----------------
__device__ __forceinline__ void layer32(const float* __restrict__ W,
                                        const float* __restrict__ B,
                                        float cur[8], int l, int do_relu)
{
    float nxt[8];
    #pragma unroll
    for (int t = 0; t < 8; t++) nxt[t] = B[l];
    #pragma unroll 4
    for (int i = 0; i < KD; i++) {
        float wv = W[i * KD + l];
        #pragma unroll
        for (int t = 0; t < 8; t++)
            nxt[t] = fmaf(__shfl_sync(FULL, cur[t], i), wv, nxt[t]);
    }
    #pragma unroll
    for (int t = 0; t < 8; t++)
        cur[t] = do_relu ? fmaxf(nxt[t], 0.0f) : nxt[t];
}

__global__ __launch_bounds__(256) void router_kernel(
    const float* __restrict__ hid,
    const float* __restrict__ w1, const float* __restrict__ b1,
    const float* __restrict__ w2, const float* __restrict__ b2,
    const float* __restrict__ w3, const float* __restrict__ b3,
    const float* __restrict__ wq, const float* __restrict__ bq,
    const float* __restrict__ unif)
{
    __shared__ float hs[64 * HD];
    const int tid = threadIdx.x;
    const int t0 = blockIdx.x * 64;
    {
        const float4* src = (const float4*)(hid + (size_t)t0 * HD);
        float4* dst = (float4*)hs;
        for (int e = tid; e < 64 * HD / 4; e += 256) dst[e] = src[e];
    }
    __syncthreads();

    const int w = tid >> 5, l = tid & 31;
    const int wt0 = w * 8;

    float cur[8];
    #pragma unroll
    for (int t = 0; t < 8; t++) cur[t] = b1[l];
    #pragma unroll 4
    for (int i = 0; i < HD; i++) {
        float wv = w1[i * KD + l];
        #pragma unroll
        for (int t = 0; t < 8; t++)
            cur[t] = fmaf(hs[(wt0 + t) * HD + i], wv, cur[t]);
    }
    #pragma unroll
    for (int t = 0; t < 8; t++) cur[t] = fmaxf(cur[t], 0.0f);

    layer32(w2, b2, cur, l, 1);
    layer32(w3, b3, cur, l, 0);
    layer32(wq, bq, cur, l, 0);

    const float scale = 0.17677669529663687f;  // 1/sqrt(32)
    int mysel = 0;
    int mytok = t0 + wt0 + l;

    #pragma unroll
    for (int t = 0; t < 8; t++) {
        float lg[NM];
        #pragma unroll
        for (int m = 0; m < NM; m++) {
            float p = cur[t] * g_kp[m * KD + l];
            #pragma unroll
            for (int off = 16; off > 0; off >>= 1)
                p += __shfl_xor_sync(FULL, p, off);
            lg[m] = p * scale;
        }
        float mx = fmaxf(fmaxf(lg[0], lg[1]), fmaxf(lg[2], lg[3]));
        float es[NM];
        float ssum = 0.0f;
        #pragma unroll
        for (int m = 0; m < NM; m++) { es[m] = expf(lg[m] - mx); ssum += es[m]; }
        float inv = 1.0f / ssum;
        int gt = t0 + wt0 + t;
        float best = -1e30f; int sel = 0;
        #pragma unroll
        for (int m = 0; m < NM; m++) {
            float u = unif[gt * NM + m];
            float gmb = -logf(-logf(u + 1e-10f) + 1e-10f);
            float y = es[m] * inv + gmb;
            if (y > best) { best = y; sel = m; }
        }
        if (l == t) mysel = sel;
    }

    #pragma unroll
    for (int m = 0; m < NM; m++) {
        unsigned mask = __ballot_sync(FULL, (l < 8) && (mysel == m));
        int base = 0;
        if (mask) {
            int leader = __ffs(mask) - 1;
            if (l == leader) base = atomicAdd(&g_cnt[m], __popc(mask));
            base = __shfl_sync(FULL, base, leader);
            if ((l < 8) && (mysel == m)) {
                int pos = base + __popc(mask & ((1u << l) - 1));
                g_idx[m * NTOK + pos] = mytok;
            }
        }
    }
}

// ---------------- main: persistent per-mechanism fused GRU agent, f32x2 math ----------------
// smem: xs [32*204] (reused as hnew [32*128]), hs [32*128], xas [32*128], toks, ticket
#define SMEM_FLOATS (TILE * IND + 2 * TILE * HD)
#define SMEM_BYTES  (SMEM_FLOATS * 4 + TILE * 4 + 16)

__global__ __launch_bounds__(128, 2) void mech_kernel(
    const float* __restrict__ x,
    const float* __restrict__ hid,
    const float* __restrict__ fc1w, const float* __restrict__ fc1b,
    const float* __restrict__ wih,  const float* __restrict__ whh,
    const float* __restrict__ bih,  const float* __restrict__ bhh,
    const float* __restrict__ fc2w, const float* __restrict__ fc2b,
    float* __restrict__ out)
{
    extern __shared__ float sm[];
    float* xs   = sm;                       // [32][204], aliased by hnew
    float* hs   = xs + TILE * IND;          // [32][128]
    float* xas  = hs + TILE * HD;           // [32][128]
    float* hnew = xs;                       // alias (xs dead after fc1)
    int*   toks = (int*)(xas + TILE * HD);  // [32]
    int*   s_tk = toks + TILE;

    const int tid = threadIdx.x;
    const int w   = tid >> 5, l = tid & 31;
    const int c0  = l * 4;
    const int tw0 = w * 8;                  // warp's first token row
    float* outH = out + (size_t)NTOK * AD;

    // per-mechanism tile prefix
    int cc[NM], pre[NM];
    int total = 0;
    #pragma unroll
    for (int m = 0; m < NM; m++) {
        cc[m] = g_cnt[m];
        total += (cc[m] + TILE - 1) / TILE;
        pre[m] = total;
    }
    if (total <= 0) return;

    for (;;) {
        if (tid == 0) *s_tk = atomicAdd(&g_ticket, 1);
        __syncthreads();
        const int tk = *s_tk;
        if (tk >= total) break;

        int m = 0;
        #pragma unroll
        for (int j = 0; j < NM - 1; j++) if (tk >= pre[j]) m = j + 1;
        const int prev = m ? pre[m - 1] : 0;
        const int t0   = (tk - prev) * TILE;
        const int nt   = min(TILE, cc[m] - t0);

        if (tid < TILE) toks[tid] = g_idx[m * NTOK + t0 + min(tid, nt - 1)];
        __syncthreads();

        // stage x and h tiles
        for (int e = tid; e < TILE * (IND / 4); e += 128) {
            int r = e / (IND / 4), c = e - r * (IND / 4);
            ((float4*)(xs + r * IND))[c] = ((const float4*)(x + (size_t)toks[r] * IND))[c];
        }
        for (int e = tid; e < TILE * (HD / 4); e += 128) {
            int r = e >> 5, c = e & 31;
            ((float4*)hs)[e] = ((const float4*)(hid + (size_t)toks[r] * HD))[c];
        }
        __syncthreads();

        const float* Wf = fc1w + m * IND * HD;
        const float* Wi = wih  + m * HD * 3 * HD;
        const float* Wh = whh  + m * HD * 3 * HD;

        // ---- fc1: xa = relu(x @ W + b); 8 tok x 4 cols per thread, f32x2 ----
        {
            u64 a[8][2];
            float4 b4 = *(const float4*)(fc1b + m * HD + c0);
            u64 bA = pk2(b4.x, b4.y), bB = pk2(b4.z, b4.w);
            #pragma unroll
            for (int t = 0; t < 8; t++) { a[t][0] = bA; a[t][1] = bB; }
            const float* xrow = xs + tw0 * IND;
            #pragma unroll 4
            for (int i = 0; i < IND; i++) {
                ulonglong2 wv = *(const ulonglong2*)(Wf + i * HD + c0);
                #pragma unroll
                for (int t = 0; t < 8; t++) {
                    u64 xp = pk2d(xrow[t * IND + i]);
                    fma2(a[t][0], xp, wv.x);
                    fma2(a[t][1], xp, wv.y);
                }
            }
            #pragma unroll
            for (int t = 0; t < 8; t++) {
                float2 v0 = unpk(a[t][0]), v1 = unpk(a[t][1]);
                float4 v;
                v.x = fmaxf(v0.x, 0.0f); v.y = fmaxf(v0.y, 0.0f);
                v.z = fmaxf(v1.x, 0.0f); v.w = fmaxf(v1.y, 0.0f);
                *(float4*)(xas + (tw0 + t) * HD + c0) = v;
            }
        }
        // no sync: xas rows are produced & consumed by the same warp

        // ---- r/z gates: 8 tok x (4r + 4z) cols, passes over Wi then Wh ----
        float rs[8][4], zs[8][4];
        {
            u64 r_[8][2], z_[8][2];
            {
                float4 bi_r = *(const float4*)(bih + m * 3 * HD + c0);
                float4 bh_r = *(const float4*)(bhh + m * 3 * HD + c0);
                float4 bi_z = *(const float4*)(bih + m * 3 * HD + HD + c0);
                float4 bh_z = *(const float4*)(bhh + m * 3 * HD + HD + c0);
                u64 rA = pk2(bi_r.x + bh_r.x, bi_r.y + bh_r.y);
                u64 rB = pk2(bi_r.z + bh_r.z, bi_r.w + bh_r.w);
                u64 zA = pk2(bi_z.x + bh_z.x, bi_z.y + bh_z.y);
                u64 zB = pk2(bi_z.z + bh_z.z, bi_z.w + bh_z.w);
                #pragma unroll
                for (int t = 0; t < 8; t++) {
                    r_[t][0] = rA; r_[t][1] = rB;
                    z_[t][0] = zA; z_[t][1] = zB;
                }
            }
            #pragma unroll 2
            for (int i = 0; i < HD; i++) {
                ulonglong2 wr = *(const ulonglong2*)(Wi + i * 3 * HD + c0);
                ulonglong2 wz = *(const ulonglong2*)(Wi + i * 3 * HD + HD + c0);
                #pragma unroll
                for (int t = 0; t < 8; t++) {
                    u64 av = pk2d(xas[(tw0 + t) * HD + i]);
                    fma2(r_[t][0], av, wr.x); fma2(r_[t][1], av, wr.y);
                    fma2(z_[t][0], av, wz.x); fma2(z_[t][1], av, wz.y);
                }
            }
            #pragma unroll 2
            for (int i = 0; i < HD; i++) {
                ulonglong2 wr = *(const ulonglong2*)(Wh + i * 3 * HD + c0);
                ulonglong2 wz = *(const ulonglong2*)(Wh + i * 3 * HD + HD + c0);
                #pragma unroll
                for (int t = 0; t < 8; t++) {
                    u64 av = pk2d(hs[(tw0 + t) * HD + i]);
                    fma2(r_[t][0], av, wr.x); fma2(r_[t][1], av, wr.y);
                    fma2(z_[t][0], av, wz.x); fma2(z_[t][1], av, wz.y);
                }
            }
            #pragma unroll
            for (int t = 0; t < 8; t++) {
                float2 a0 = unpk(r_[t][0]), a1 = unpk(r_[t][1]);
                float2 b0 = unpk(z_[t][0]), b1 = unpk(z_[t][1]);
                rs[t][0] = sigmf(a0.x); rs[t][1] = sigmf(a0.y);
                rs[t][2] = sigmf(a1.x); rs[t][3] = sigmf(a1.y);
                zs[t][0] = sigmf(b0.x); zs[t][1] = sigmf(b0.y);
                zs[t][2] = sigmf(b1.x); zs[t][3] = sigmf(b1.y);
            }
        }

        // ---- n gate: inn (xa @ Wi_n) and hn (h @ Wh_n) ----
        {
            u64 n_[8][2], q_[8][2];
            {
                float4 bn  = *(const float4*)(bih + m * 3 * HD + 2 * HD + c0);
                float4 bhn = *(const float4*)(bhh + m * 3 * HD + 2 * HD + c0);
                u64 nA = pk2(bn.x, bn.y),  nB = pk2(bn.z, bn.w);
                u64 qA = pk2(bhn.x, bhn.y), qB = pk2(bhn.z, bhn.w);
                #pragma unroll
                for (int t = 0; t < 8; t++) {
                    n_[t][0] = nA; n_[t][1] = nB;
                    q_[t][0] = qA; q_[t][1] = qB;
                }
            }
            #pragma unroll 2
            for (int i = 0; i < HD; i++) {
                ulonglong2 wn  = *(const ulonglong2*)(Wi + i * 3 * HD + 2 * HD + c0);
                ulonglong2 whn = *(const ulonglong2*)(Wh + i * 3 * HD + 2 * HD + c0);
                #pragma unroll
                for (int t = 0; t < 8; t++) {
                    u64 xv = pk2d(xas[(tw0 + t) * HD + i]);
                    u64 hv = pk2d(hs[(tw0 + t) * HD + i]);
                    fma2(n_[t][0], xv, wn.x);  fma2(n_[t][1], xv, wn.y);
                    fma2(q_[t][0], hv, whn.x); fma2(q_[t][1], hv, whn.y);
                }
            }
            // combine: h' = (1-z)*tanh(inn + r*hn) + z*h
            #pragma unroll
            for (int t = 0; t < 8; t++) {
                int j = tw0 + t;
                float2 n0 = unpk(n_[t][0]), n1 = unpk(n_[t][1]);
                float2 q0 = unpk(q_[t][0]), q1 = unpk(q_[t][1]);
                float4 hv = *(float4*)(hs + j * HD + c0);
                float g0 = tanhf(n0.x + rs[t][0] * q0.x);
                float g1 = tanhf(n0.y + rs[t][1] * q0.y);
                float g2 = tanhf(n1.x + rs[t][2] * q1.x);
                float g3 = tanhf(n1.y + rs[t][3] * q1.y);
                float4 o;
                o.x = (1.0f - zs[t][0]) * g0 + zs[t][0] * hv.x;
                o.y = (1.0f - zs[t][1]) * g1 + zs[t][1] * hv.y;
                o.z = (1.0f - zs[t][2]) * g2 + zs[t][2] * hv.z;
                o.w = (1.0f - zs[t][3]) * g3 + zs[t][3] * hv.w;
                *(float4*)(hnew + j * HD + c0) = o;
                if (j < nt)
                    *(float4*)(outH + (size_t)toks[j] * HD + c0) = o;
            }
        }
        __syncthreads();   // hnew visible to all threads for fc2

        // ---- fc2: q = h_new @ fc2_w + fc2_b ----
        for (int oi = tid; oi < TILE * AD; oi += 128) {
            int t = oi / AD, a = oi - t * AD;
            if (t < nt) {
                float acc = fc2b[m * AD + a];
                const float* wp = fc2w + m * HD * AD + a;
                const float* hp = hnew + t * HD;
                #pragma unroll 4
                for (int i = 0; i < HD; i++)
                    acc = fmaf(hp[i], __ldg(wp + i * AD), acc);
                out[(size_t)toks[t] * AD + a] = acc;
            }
        }
        // ticket-broadcast sync at loop head separates fc2 reads from restaging
    }
}

// ---------------- launch ----------------
extern "C" void kernel_launch(void* const* d_in, const int* in_sizes, int n_in,
                              void* d_out, int out_size)
{
    const float* x    = (const float*)d_in[0];
    const float* hid  = (const float*)d_in[1];
    const float* fc1w = (const float*)d_in[2];
    const float* fc1b = (const float*)d_in[3];
    const float* wih  = (const float*)d_in[4];
    const float* whh  = (const float*)d_in[5];
    const float* bih  = (const float*)d_in[6];
    const float* bhh  = (const float*)d_in[7];
    const float* fc2w = (const float*)d_in[8];
    const float* fc2b = (const float*)d_in[9];
    const float* w1   = (const float*)d_in[10];
    const float* b1   = (const float*)d_in[11];
    const float* w2   = (const float*)d_in[12];
    const float* b2   = (const float*)d_in[13];
    const float* w3   = (const float*)d_in[14];
    const float* b3   = (const float*)d_in[15];
    const float* mk   = (const float*)d_in[16];
    const float* wq   = (const float*)d_in[17];
    const float* bq   = (const float*)d_in[18];
    const float* wk   = (const float*)d_in[19];
    const float* bk   = (const float*)d_in[20];
    const float* unif = (const float*)d_in[21];
    float* out = (float*)d_out;

    cudaFuncSetAttribute(mech_kernel, cudaFuncAttributeMaxDynamicSharedMemorySize, SMEM_BYTES);

    kp_kernel<<<1, 128>>>(mk, wk, bk);
    router_kernel<<<NTOK / 64, 256>>>(hid, w1, b1, w2, b2, w3, b3, wq, bq, unif);
    mech_kernel<<<320, 128, SMEM_BYTES>>>(x, hid, fc1w, fc1b, wih, whh,
                                          bih, bhh, fc2w, fc2b, out);
}

// round 7
// speedup vs baseline: 1.7664x; 1.7664x over previous
#include <cuda_runtime.h>
#include <math.h>
#include <stdint.h>

#define NTOK 32768
#define NM   4
#define IND  204
#define HD   128
#define AD   14
#define KD   32
#define TT   64
#define FULL 0xffffffffu

#define PITCH   264
#define XPITCH  212
#define OFF_PR  16896
#define OFF_PN  33792
#define OFF_TOK 50688
#define SMEM_BYTES ((OFF_TOK + 80) * 4)

// ---------------- device scratch ----------------
__device__ float    g_kp[NM * KD];
__device__ int      g_cnt[NM];
__device__ int      g_ticket;
__device__ int      g_idx[NM * NTOK];
// B-fragment-packed tf32 weight images: [kb][n][8] with (k,k+4) pairs adjacent
__device__ __align__(128) uint32_t g_bf1[NM * 26 * 128 * 8];   // fc1: K=208(pad), N=128
__device__ __align__(128) uint32_t g_brz[NM * 32 * 256 * 8];   // r|z: K=256 ([Wi;Wh]), N=256 ([r|z])
__device__ __align__(128) uint32_t g_bnq[NM * 16 * 256 * 8];   // inn|hn: K=128, N=256 ([inn|hn])

__device__ __forceinline__ float sigmf(float v) { return 1.0f / (1.0f + __expf(-v)); }
__device__ __forceinline__ uint32_t f2tf(float f) {
    uint32_t r; asm("cvt.rna.tf32.f32 %0,%1;" : "=r"(r) : "f"(f)); return r;
}
__device__ __forceinline__ void mma8(float c[4], const uint32_t a[4], uint2 b) {
    asm volatile("mma.sync.aligned.m16n8k8.row.col.f32.tf32.tf32.f32 "
                 "{%0,%1,%2,%3},{%4,%5,%6,%7},{%8,%9},{%0,%1,%2,%3};"
                 : "+f"(c[0]), "+f"(c[1]), "+f"(c[2]), "+f"(c[3])
                 : "r"(a[0]), "r"(a[1]), "r"(a[2]), "r"(a[3]), "r"(b.x), "r"(b.y));
}

// ---------------- kernel 0: keys + resets ----------------
__global__ void kp_kernel(const float* __restrict__ mech_keys,
                          const float* __restrict__ wk,
                          const float* __restrict__ bk)
{
    int tid = threadIdx.x;
    if (tid == 0) g_ticket = 0;
    if (tid < NM) g_cnt[tid] = 0;
    if (tid < NM * KD) {
        int m = tid >> 5, k = tid & 31;
        float acc = bk[k];
        #pragma unroll
        for (int i = 0; i < KD; i++)
            acc = fmaf(mech_keys[m * KD + i], wk[i * KD + k], acc);
        g_kp[tid] = acc;
    }
}

// ---------------- prep: pack weights into B-fragment tf32 images ----------------
#define NBF1 (NM * 26 * 128 * 8)
#define NBRZ (NM * 32 * 256 * 8)
#define NBNQ (NM * 16 * 256 * 8)
__global__ void prep_kernel(const float* __restrict__ fc1w,
                            const float* __restrict__ wih,
                            const float* __restrict__ whh)
{
    int e = blockIdx.x * blockDim.x + threadIdx.x;
    if (e < NBF1) {
        int m = e / 26624, r = e % 26624;
        int kb = r / 1024, r2 = r % 1024;
        int n = r2 >> 3, p = r2 & 7;
        int k = kb * 8 + (p >> 1) + ((p & 1) << 2);
        float v = (k < IND) ? fc1w[((size_t)m * IND + k) * HD + n] : 0.0f;
        g_bf1[e] = f2tf(v);
    } else if (e < NBF1 + NBRZ) {
        int e2 = e - NBF1;
        int m = e2 / 65536, r = e2 % 65536;
        int kb = r / 2048, r2 = r % 2048;
        int n = r2 >> 3, p = r2 & 7;
        int k = kb * 8 + (p >> 1) + ((p & 1) << 2);
        int gate = n >> 7, col = n & 127;
        float v = (k < 128) ? wih[((size_t)m * HD + k) * 384 + gate * 128 + col]
                            : whh[((size_t)m * HD + (k - 128)) * 384 + gate * 128 + col];
        g_brz[e2] = f2tf(v);
    } else if (e < NBF1 + NBRZ + NBNQ) {
        int e3 = e - NBF1 - NBRZ;
        int m = e3 / 32768, r = e3 % 32768;
        int kb = r / 2048, r2 = r % 2048;
        int n = r2 >> 3, p = r2 & 7;
        int k = kb * 8 + (p >> 1) + ((p & 1) << 2);
        int sel = n >> 7, col = n & 127;
        float v = (sel == 0) ? wih[((size_t)m * HD + k) * 384 + 256 + col]
                             : whh[((size_t)m * HD + k) * 384 + 256 + col];
        g_bnq[e3] = f2tf(v);
    }
}

// ---------------- router (proven fp32 path, unchanged) ----------------
__device__ __forceinline__ void layer32(const float* __restrict__ W,
                                        const float* __restrict__ B,
                                        float cur[8], int l, int do_relu)
{
    float nxt[8];
    #pragma unroll
    for (int t = 0; t < 8; t++) nxt[t] = B[l];
    #pragma unroll 4
    for (int i = 0; i < KD; i++) {
        float wv = W[i * KD + l];
        #pragma unroll
        for (int t = 0; t < 8; t++)
            nxt[t] = fmaf(__shfl_sync(FULL, cur[t], i), wv, nxt[t]);
    }
    #pragma unroll
    for (int t = 0; t < 8; t++)
        cur[t] = do_relu ? fmaxf(nxt[t], 0.0f) : nxt[t];
}

__global__ __launch_bounds__(256) void router_kernel(
    const float* __restrict__ hid,
    const float* __restrict__ w1, const float* __restrict__ b1,
    const float* __restrict__ w2, const float* __restrict__ b2,
    const float* __restrict__ w3, const float* __restrict__ b3,
    const float* __restrict__ wq, const float* __restrict__ bq,
    const float* __restrict__ unif)
{
    __shared__ float hs[64 * HD];
    const int tid = threadIdx.x;
    const int t0 = blockIdx.x * 64;
    {
        const float4* src = (const float4*)(hid + (size_t)t0 * HD);
        float4* dst = (float4*)hs;
        for (int e = tid; e < 64 * HD / 4; e += 256) dst[e] = src[e];
    }
    __syncthreads();
    const int w = tid >> 5, l = tid & 31;
    const int wt0 = w * 8;
    float cur[8];
    #pragma unroll
    for (int t = 0; t < 8; t++) cur[t] = b1[l];
    #pragma unroll 4
    for (int i = 0; i < HD; i++) {
        float wv = w1[i * KD + l];
        #pragma unroll
        for (int t = 0; t < 8; t++)
            cur[t] = fmaf(hs[(wt0 + t) * HD + i], wv, cur[t]);
    }
    #pragma unroll
    for (int t = 0; t < 8; t++) cur[t] = fmaxf(cur[t], 0.0f);
    layer32(w2, b2, cur, l, 1);
    layer32(w3, b3, cur, l, 0);
    layer32(wq, bq, cur, l, 0);

    const float scale = 0.17677669529663687f;
    int mysel = 0;
    int mytok = t0 + wt0 + l;
    #pragma unroll
    for (int t = 0; t < 8; t++) {
        float lg[NM];
        #pragma unroll
        for (int m = 0; m < NM; m++) {
            float p = cur[t] * g_kp[m * KD + l];
            #pragma unroll
            for (int off = 16; off > 0; off >>= 1)
                p += __shfl_xor_sync(FULL, p, off);
            lg[m] = p * scale;
        }
        float mx = fmaxf(fmaxf(lg[0], lg[1]), fmaxf(lg[2], lg[3]));
        float es[NM]; float ssum = 0.0f;
        #pragma unroll
        for (int m = 0; m < NM; m++) { es[m] = expf(lg[m] - mx); ssum += es[m]; }
        float inv = 1.0f / ssum;
        int gt = t0 + wt0 + t;
        float best = -1e30f; int sel = 0;
        #pragma unroll
        for (int m = 0; m < NM; m++) {
            float u = unif[gt * NM + m];
            float gmb = -logf(-logf(u + 1e-10f) + 1e-10f);
            float y = es[m] * inv + gmb;
            if (y > best) { best = y; sel = m; }
        }
        if (l == t) mysel = sel;
    }
    #pragma unroll
    for (int m = 0; m < NM; m++) {
        unsigned mask = __ballot_sync(FULL, (l < 8) && (mysel == m));
        if (mask) {
            int leader = __ffs(mask) - 1;
            int base = 0;
            if (l == leader) base = atomicAdd(&g_cnt[m], __popc(mask));
            base = __shfl_sync(FULL, base, leader);
            if ((l < 8) && (mysel == m)) {
                int pos = base + __popc(mask & ((1u << l) - 1));
                g_idx[m * NTOK + pos] = mytok;
            }
        }
    }
}

// ---------------- mech: persistent mma.sync-tf32 fused GRU agent ----------------
__global__ __launch_bounds__(256, 1) void mech_kernel(
    const float* __restrict__ x, const float* __restrict__ hid,
    const float* __restrict__ fc1b,
    const float* __restrict__ bih, const float* __restrict__ bhh,
    const float* __restrict__ fc2w, const float* __restrict__ fc2b,
    float* __restrict__ out)
{
    extern __shared__ float sm[];
    float* Gp = sm;                 // [64][264] pair-interleaved: cols 0-127 XA, 128-255 H
    float* PR = sm + OFF_PR;        // [64][264] plain: r | z preacts; later Hnew in 0-127
    float* PN = sm + OFF_PN;        // [64][264] plain: inn | hn preacts (aliases Xp)
    float* Xp = PN;                 // [64][212] pair-interleaved X (dead after fc1)
    int* toks = (int*)(sm + OFF_TOK);
    int* s_tk = toks + TT;

    const int tid = threadIdx.x;
    const int w = tid >> 5, l = tid & 31;
    const int gr = l >> 2, gc = l & 3;
    float* outH = out + (size_t)NTOK * AD;

    int cc[NM], pre[NM]; int total = 0;
    #pragma unroll
    for (int m = 0; m < NM; m++) {
        cc[m] = g_cnt[m];
        total += (cc[m] + TT - 1) / TT;
        pre[m] = total;
    }

    for (;;) {
        if (tid == 0) *s_tk = atomicAdd(&g_ticket, 1);
        __syncthreads();
        const int tk = *s_tk;
        if (tk >= total) break;
        int m = 0;
        #pragma unroll
        for (int j = 0; j < NM - 1; j++) if (tk >= pre[j]) m = j + 1;
        const int prev = m ? pre[m - 1] : 0;
        const int t0 = (tk - prev) * TT;
        const int nt = min(TT, cc[m] - t0);
        if (tid < TT) toks[tid] = g_idx[m * NTOK + t0 + min(tid, nt - 1)];
        __syncthreads();

        // ---- stage X pair-interleaved into Xp ----
        for (int e = tid; e < TT * 52; e += 256) {
            int r = e / 52, c4 = e % 52;
            float4 v = make_float4(0.f, 0.f, 0.f, 0.f);
            if (c4 < 51) v = ((const float4*)(x + (size_t)toks[r] * IND))[c4];
            int k0 = c4 * 4;
            float* dst = Xp + r * XPITCH + ((k0 >> 3) << 3) + ((k0 & 7) >> 2);
            dst[0] = v.x; dst[2] = v.y; dst[4] = v.z; dst[6] = v.w;
        }
        // ---- stage H pair-interleaved into Gp cols 128.. ----
        for (int e = tid; e < TT * 32; e += 256) {
            int r = e >> 5, c4 = e & 31;
            float4 v = ((const float4*)(hid + (size_t)toks[r] * HD))[c4];
            int k0 = 128 + c4 * 4;
            float* dst = Gp + r * PITCH + ((k0 >> 3) << 3) + ((k0 & 7) >> 2);
            dst[0] = v.x; dst[2] = v.y; dst[4] = v.z; dst[6] = v.w;
        }
        __syncthreads();

        // ---- fc1: warp = m32 x n32 (band = w>>2, ng = w&3) ----
        {
            const int band = w >> 2, ng = w & 3;
            float c[2][4][4];
            #pragma unroll
            for (int nt_ = 0; nt_ < 4; nt_++) {
                int col = ng * 32 + nt_ * 8 + gc * 2;
                float b0 = __ldg(fc1b + m * HD + col);
                float b1 = __ldg(fc1b + m * HD + col + 1);
                #pragma unroll
                for (int mt = 0; mt < 2; mt++) {
                    c[mt][nt_][0] = b0; c[mt][nt_][1] = b1;
                    c[mt][nt_][2] = b0; c[mt][nt_][3] = b1;
                }
            }
            const uint32_t* Bb = g_bf1 + m * 26624;
            #pragma unroll 2
            for (int kb = 0; kb < 26; kb++) {
                uint32_t a[2][4];
                #pragma unroll
                for (int mt = 0; mt < 2; mt++) {
                    int row = band * 32 + mt * 16 + gr;
                    float2 lo = *(const float2*)(Xp + row * XPITCH + kb * 8 + gc * 2);
                    float2 hi = *(const float2*)(Xp + (row + 8) * XPITCH + kb * 8 + gc * 2);
                    a[mt][0] = f2tf(lo.x); a[mt][1] = f2tf(hi.x);
                    a[mt][2] = f2tf(lo.y); a[mt][3] = f2tf(hi.y);
                }
                uint2 b[4];
                #pragma unroll
                for (int nt_ = 0; nt_ < 4; nt_++)
                    b[nt_] = __ldg((const uint2*)(Bb + (kb * 128 + ng * 32 + nt_ * 8 + gr) * 8 + gc * 2));
                #pragma unroll
                for (int mt = 0; mt < 2; mt++)
                    #pragma unroll
                    for (int nt_ = 0; nt_ < 4; nt_++)
                        mma8(c[mt][nt_], a[mt], b[nt_]);
            }
            // relu + write XA pair-interleaved into Gp cols 0-127
            #pragma unroll
            for (int mt = 0; mt < 2; mt++)
                #pragma unroll
                for (int nt_ = 0; nt_ < 4; nt_++) {
                    int row = band * 32 + mt * 16 + gr;
                    int col = ng * 32 + nt_ * 8 + gc * 2;
                    int p = ((col >> 3) << 3) + ((col & 3) << 1) + ((col & 7) >> 2);
                    Gp[row * PITCH + p]           = fmaxf(c[mt][nt_][0], 0.f);
                    Gp[row * PITCH + p + 2]       = fmaxf(c[mt][nt_][1], 0.f);
                    Gp[(row + 8) * PITCH + p]     = fmaxf(c[mt][nt_][2], 0.f);
                    Gp[(row + 8) * PITCH + p + 2] = fmaxf(c[mt][nt_][3], 0.f);
                }
        }
        __syncthreads();

        // ---- gates: pair = w>>2 (0: r/inn, 1: z/hn), ng = w&3; warp = m64 x n32 ----
        {
            const int pair = w >> 2, ng = w & 3;
            // -- r|z: K=256 over Gp concat [XA|H] --
            {
                float c[4][4][4];
                #pragma unroll
                for (int nt_ = 0; nt_ < 4; nt_++) {
                    int col = ng * 32 + nt_ * 8 + gc * 2;
                    float b0 = __ldg(bih + m * 384 + pair * 128 + col) + __ldg(bhh + m * 384 + pair * 128 + col);
                    float b1 = __ldg(bih + m * 384 + pair * 128 + col + 1) + __ldg(bhh + m * 384 + pair * 128 + col + 1);
                    #pragma unroll
                    for (int mt = 0; mt < 4; mt++) {
                        c[mt][nt_][0] = b0; c[mt][nt_][1] = b1;
                        c[mt][nt_][2] = b0; c[mt][nt_][3] = b1;
                    }
                }
                const uint32_t* Bb = g_brz + m * 65536;
                #pragma unroll 2
                for (int kb = 0; kb < 32; kb++) {
                    uint32_t a[4][4];
                    #pragma unroll
                    for (int mt = 0; mt < 4; mt++) {
                        int row = mt * 16 + gr;
                        float2 lo = *(const float2*)(Gp + row * PITCH + kb * 8 + gc * 2);
                        float2 hi = *(const float2*)(Gp + (row + 8) * PITCH + kb * 8 + gc * 2);
                        a[mt][0] = f2tf(lo.x); a[mt][1] = f2tf(hi.x);
                        a[mt][2] = f2tf(lo.y); a[mt][3] = f2tf(hi.y);
                    }
                    uint2 b[4];
                    #pragma unroll
                    for (int nt_ = 0; nt_ < 4; nt_++)
                        b[nt_] = __ldg((const uint2*)(Bb + (kb * 256 + pair * 128 + ng * 32 + nt_ * 8 + gr) * 8 + gc * 2));
                    #pragma unroll
                    for (int mt = 0; mt < 4; mt++)
                        #pragma unroll
                        for (int nt_ = 0; nt_ < 4; nt_++)
                            mma8(c[mt][nt_], a[mt], b[nt_]);
                }
                #pragma unroll
                for (int mt = 0; mt < 4; mt++)
                    #pragma unroll
                    for (int nt_ = 0; nt_ < 4; nt_++) {
                        int row = mt * 16 + gr;
                        int col = pair * 128 + ng * 32 + nt_ * 8 + gc * 2;
                        *(float2*)(PR + row * PITCH + col)       = make_float2(c[mt][nt_][0], c[mt][nt_][1]);
                        *(float2*)(PR + (row + 8) * PITCH + col) = make_float2(c[mt][nt_][2], c[mt][nt_][3]);
                    }
            }
            // -- inn|hn: K=128 (XA half for pair=0, H half for pair=1) --
            {
                float c[4][4][4];
                #pragma unroll
                for (int nt_ = 0; nt_ < 4; nt_++) {
                    int col = ng * 32 + nt_ * 8 + gc * 2;
                    const float* bsrc = pair ? bhh : bih;
                    float b0 = __ldg(bsrc + m * 384 + 256 + col);
                    float b1 = __ldg(bsrc + m * 384 + 256 + col + 1);
                    #pragma unroll
                    for (int mt = 0; mt < 4; mt++) {
                        c[mt][nt_][0] = b0; c[mt][nt_][1] = b1;
                        c[mt][nt_][2] = b0; c[mt][nt_][3] = b1;
                    }
                }
                const uint32_t* Bb = g_bnq + m * 32768;
                const int kab = pair * 16;
                #pragma unroll 2
                for (int kb = 0; kb < 16; kb++) {
                    uint32_t a[4][4];
                    #pragma unroll
                    for (int mt = 0; mt < 4; mt++) {
                        int row = mt * 16 + gr;
                        float2 lo = *(const float2*)(Gp + row * PITCH + (kab + kb) * 8 + gc * 2);
                        float2 hi = *(const float2*)(Gp + (row + 8) * PITCH + (kab + kb) * 8 + gc * 2);
                        a[mt][0] = f2tf(lo.x); a[mt][1] = f2tf(hi.x);
                        a[mt][2] = f2tf(lo.y); a[mt][3] = f2tf(hi.y);
                    }
                    uint2 b[4];
                    #pragma unroll
                    for (int nt_ = 0; nt_ < 4; nt_++)
                        b[nt_] = __ldg((const uint2*)(Bb + (kb * 256 + pair * 128 + ng * 32 + nt_ * 8 + gr) * 8 + gc * 2));
                    #pragma unroll
                    for (int mt = 0; mt < 4; mt++)
                        #pragma unroll
                        for (int nt_ = 0; nt_ < 4; nt_++)
                            mma8(c[mt][nt_], a[mt], b[nt_]);
                }
                #pragma unroll
                for (int mt = 0; mt < 4; mt++)
                    #pragma unroll
                    for (int nt_ = 0; nt_ < 4; nt_++) {
                        int row = mt * 16 + gr;
                        int col = pair * 128 + ng * 32 + nt_ * 8 + gc * 2;
                        *(float2*)(PN + row * PITCH + col)       = make_float2(c[mt][nt_][0], c[mt][nt_][1]);
                        *(float2*)(PN + (row + 8) * PITCH + col) = make_float2(c[mt][nt_][2], c[mt][nt_][3]);
                    }
            }
        }
        __syncthreads();

        // ---- GRU elementwise epilogue ----
        for (int e = tid; e < TT * HD; e += 256) {
            int t = e >> 7, o = e & 127;
            float rv = sigmf(PR[t * PITCH + o]);
            float zv = sigmf(PR[t * PITCH + 128 + o]);
            float nv = PN[t * PITCH + o];
            float qv = PN[t * PITCH + 128 + o];
            int ko = 128 + o;
            float hv = Gp[t * PITCH + ((ko >> 3) << 3) + ((ko & 3) << 1) + ((ko & 7) >> 2)];
            float gg = tanhf(nv + rv * qv);
            float hn2 = (1.0f - zv) * gg + zv * hv;
            PR[t * PITCH + o] = hn2;
            outH[(size_t)toks[t] * HD + o] = hn2;
        }
        __syncthreads();

        // ---- fc2 ----
        for (int oi = tid; oi < TT * AD; oi += 256) {
            int t = oi / AD, a = oi - t * AD;
            float acc = fc2b[m * AD + a];
            const float* wp = fc2w + m * HD * AD + a;
            const float* hp = PR + t * PITCH;
            #pragma unroll 4
            for (int i = 0; i < HD; i++)
                acc = fmaf(hp[i], __ldg(wp + i * AD), acc);
            out[(size_t)toks[t] * AD + a] = acc;
        }
        // loop-head sync orders next-tile staging after fc2 reads
    }
}

// ---------------- launch ----------------
extern "C" void kernel_launch(void* const* d_in, const int* in_sizes, int n_in,
                              void* d_out, int out_size)
{
    const float* x    = (const float*)d_in[0];
    const float* hid  = (const float*)d_in[1];
    const float* fc1w = (const float*)d_in[2];
    const float* fc1b = (const float*)d_in[3];
    const float* wih  = (const float*)d_in[4];
    const float* whh  = (const float*)d_in[5];
    const float* bih  = (const float*)d_in[6];
    const float* bhh  = (const float*)d_in[7];
    const float* fc2w = (const float*)d_in[8];
    const float* fc2b = (const float*)d_in[9];
    const float* w1   = (const float*)d_in[10];
    const float* b1   = (const float*)d_in[11];
    const float* w2   = (const float*)d_in[12];
    const float* b2   = (const float*)d_in[13];
    const float* w3   = (const float*)d_in[14];
    const float* b3   = (const float*)d_in[15];
    const float* mk   = (const float*)d_in[16];
    const float* wq   = (const float*)d_in[17];
    const float* bq   = (const float*)d_in[18];
    const float* wk   = (const float*)d_in[19];
    const float* bk   = (const float*)d_in[20];
    const float* unif = (const float*)d_in[21];
    float* out = (float*)d_out;

    cudaFuncSetAttribute(mech_kernel, cudaFuncAttributeMaxDynamicSharedMemorySize, SMEM_BYTES);

    kp_kernel<<<1, 128>>>(mk, wk, bk);
    {
        int tot = NBF1 + NBRZ + NBNQ;
        prep_kernel<<<(tot + 255) / 256, 256>>>(fc1w, wih, whh);
    }
    router_kernel<<<NTOK / 64, 256>>>(hid, w1, b1, w2, b2, w3, b3, wq, bq, unif);
    mech_kernel<<<148, 256, SMEM_BYTES>>>(x, hid, fc1b, bih, bhh, fc2w, fc2b, out);
}

// round 8
// speedup vs baseline: 2.1786x; 1.2334x over previous
#include <cuda_runtime.h>
#include <math.h>
#include <stdint.h>

#define NTOK 32768
#define NM   4
#define IND  204
#define HD   128
#define AD   14
#define KD   32
#define TT   64
#define NTHR 512
#define FULL 0xffffffffu

#define PITCH   264
#define XPITCH  212
#define OFF_PR  16896
#define OFF_PN  33792
#define OFF_TOK 50688
#define SMEM_BYTES ((OFF_TOK + 80) * 4)

// ---------------- device scratch ----------------
__device__ float    g_kp[NM * KD];
__device__ int      g_cnt[NM];
__device__ int      g_ticket;
__device__ int      g_idx[NM * NTOK];
// B-fragment-packed tf32 weight images: [kb][n][8] with (k,k+4) pairs adjacent
__device__ __align__(128) uint32_t g_bf1[NM * 26 * 128 * 8];   // fc1: K=208(pad), N=128
__device__ __align__(128) uint32_t g_brz[NM * 32 * 256 * 8];   // r|z: K=256 ([Wi;Wh]), N=256 ([r|z])
__device__ __align__(128) uint32_t g_bnq[NM * 16 * 256 * 8];   // inn|hn: K=128, N=256 ([inn|hn])

__device__ __forceinline__ float sigmf(float v) { return 1.0f / (1.0f + __expf(-v)); }
__device__ __forceinline__ uint32_t f2tf(float f) {
    uint32_t r; asm("cvt.rna.tf32.f32 %0,%1;" : "=r"(r) : "f"(f)); return r;
}
__device__ __forceinline__ void mma8(float c[4], const uint32_t a[4], uint2 b) {
    asm volatile("mma.sync.aligned.m16n8k8.row.col.f32.tf32.tf32.f32 "
                 "{%0,%1,%2,%3},{%4,%5,%6,%7},{%8,%9},{%0,%1,%2,%3};"
                 : "+f"(c[0]), "+f"(c[1]), "+f"(c[2]), "+f"(c[3])
                 : "r"(a[0]), "r"(a[1]), "r"(a[2]), "r"(a[3]), "r"(b.x), "r"(b.y));
}

// ---------------- kernel 0: keys + resets ----------------
__global__ void kp_kernel(const float* __restrict__ mech_keys,
                          const float* __restrict__ wk,
                          const float* __restrict__ bk)
{
    int tid = threadIdx.x;
    if (tid == 0) g_ticket = 0;
    if (tid < NM) g_cnt[tid] = 0;
    if (tid < NM * KD) {
        int m = tid >> 5, k = tid & 31;
        float acc = bk[k];
        #pragma unroll
        for (int i = 0; i < KD; i++)
            acc = fmaf(mech_keys[m * KD + i], wk[i * KD + k], acc);
        g_kp[tid] = acc;
    }
}

// ---------------- prep: pack weights into B-fragment tf32 images ----------------
#define NBF1 (NM * 26 * 128 * 8)
#define NBRZ (NM * 32 * 256 * 8)
#define NBNQ (NM * 16 * 256 * 8)
__global__ void prep_kernel(const float* __restrict__ fc1w,
                            const float* __restrict__ wih,
                            const float* __restrict__ whh)
{
    int e = blockIdx.x * blockDim.x + threadIdx.x;
    if (e < NBF1) {
        int m = e / 26624, r = e % 26624;
        int kb = r / 1024, r2 = r % 1024;
        int n = r2 >> 3, p = r2 & 7;
        int k = kb * 8 + (p >> 1) + ((p & 1) << 2);
        float v = (k < IND) ? fc1w[((size_t)m * IND + k) * HD + n] : 0.0f;
        g_bf1[e] = f2tf(v);
    } else if (e < NBF1 + NBRZ) {
        int e2 = e - NBF1;
        int m = e2 / 65536, r = e2 % 65536;
        int kb = r / 2048, r2 = r % 2048;
        int n = r2 >> 3, p = r2 & 7;
        int k = kb * 8 + (p >> 1) + ((p & 1) << 2);
        int gate = n >> 7, col = n & 127;
        float v = (k < 128) ? wih[((size_t)m * HD + k) * 384 + gate * 128 + col]
                            : whh[((size_t)m * HD + (k - 128)) * 384 + gate * 128 + col];
        g_brz[e2] = f2tf(v);
    } else if (e < NBF1 + NBRZ + NBNQ) {
        int e3 = e - NBF1 - NBRZ;
        int m = e3 / 32768, r = e3 % 32768;
        int kb = r / 2048, r2 = r % 2048;
        int n = r2 >> 3, p = r2 & 7;
        int k = kb * 8 + (p >> 1) + ((p & 1) << 2);
        int sel = n >> 7, col = n & 127;
        float v = (sel == 0) ? wih[((size_t)m * HD + k) * 384 + 256 + col]
                             : whh[((size_t)m * HD + k) * 384 + 256 + col];
        g_bnq[e3] = f2tf(v);
    }
}

// ---------------- router (proven fp32 path, unchanged) ----------------
__device__ __forceinline__ void layer32(const float* __restrict__ W,
                                        const float* __restrict__ B,
                                        float cur[8], int l, int do_relu)
{
    float nxt[8];
    #pragma unroll
    for (int t = 0; t < 8; t++) nxt[t] = B[l];
    #pragma unroll 4
    for (int i = 0; i < KD; i++) {
        float wv = W[i * KD + l];
        #pragma unroll
        for (int t = 0; t < 8; t++)
            nxt[t] = fmaf(__shfl_sync(FULL, cur[t], i), wv, nxt[t]);
    }
    #pragma unroll
    for (int t = 0; t < 8; t++)
        cur[t] = do_relu ? fmaxf(nxt[t], 0.0f) : nxt[t];
}

__global__ __launch_bounds__(256) void router_kernel(
    const float* __restrict__ hid,
    const float* __restrict__ w1, const float* __restrict__ b1,
    const float* __restrict__ w2, const float* __restrict__ b2,
    const float* __restrict__ w3, const float* __restrict__ b3,
    const float* __restrict__ wq, const float* __restrict__ bq,
    const float* __restrict__ unif)
{
    __shared__ float hs[64 * HD];
    const int tid = threadIdx.x;
    const int t0 = blockIdx.x * 64;
    {
        const float4* src = (const float4*)(hid + (size_t)t0 * HD);
        float4* dst = (float4*)hs;
        for (int e = tid; e < 64 * HD / 4; e += 256) dst[e] = src[e];
    }
    __syncthreads();
    const int w = tid >> 5, l = tid & 31;
    const int wt0 = w * 8;
    float cur[8];
    #pragma unroll
    for (int t = 0; t < 8; t++) cur[t] = b1[l];
    #pragma unroll 4
    for (int i = 0; i < HD; i++) {
        float wv = w1[i * KD + l];
        #pragma unroll
        for (int t = 0; t < 8; t++)
            cur[t] = fmaf(hs[(wt0 + t) * HD + i], wv, cur[t]);
    }
    #pragma unroll
    for (int t = 0; t < 8; t++) cur[t] = fmaxf(cur[t], 0.0f);
    layer32(w2, b2, cur, l, 1);
    layer32(w3, b3, cur, l, 0);
    layer32(wq, bq, cur, l, 0);

    const float scale = 0.17677669529663687f;
    int mysel = 0;
    int mytok = t0 + wt0 + l;
    #pragma unroll
    for (int t = 0; t < 8; t++) {
        float lg[NM];
        #pragma unroll
        for (int m = 0; m < NM; m++) {
            float p = cur[t] * g_kp[m * KD + l];
            #pragma unroll
            for (int off = 16; off > 0; off >>= 1)
                p += __shfl_xor_sync(FULL, p, off);
            lg[m] = p * scale;
        }
        float mx = fmaxf(fmaxf(lg[0], lg[1]), fmaxf(lg[2], lg[3]));
        float es[NM]; float ssum = 0.0f;
        #pragma unroll
        for (int m = 0; m < NM; m++) { es[m] = expf(lg[m] - mx); ssum += es[m]; }
        float inv = 1.0f / ssum;
        int gt = t0 + wt0 + t;
        float best = -1e30f; int sel = 0;
        #pragma unroll
        for (int m = 0; m < NM; m++) {
            float u = unif[gt * NM + m];
            float gmb = -logf(-logf(u + 1e-10f) + 1e-10f);
            float y = es[m] * inv + gmb;
            if (y > best) { best = y; sel = m; }
        }
        if (l == t) mysel = sel;
    }
    #pragma unroll
    for (int m = 0; m < NM; m++) {
        unsigned mask = __ballot_sync(FULL, (l < 8) && (mysel == m));
        if (mask) {
            int leader = __ffs(mask) - 1;
            int base = 0;
            if (l == leader) base = atomicAdd(&g_cnt[m], __popc(mask));
            base = __shfl_sync(FULL, base, leader);
            if ((l < 8) && (mysel == m)) {
                int pos = base + __popc(mask & ((1u << l) - 1));
                g_idx[m * NTOK + pos] = mytok;
            }
        }
    }
}

// ---------------- mech: persistent mma.sync-tf32 fused GRU agent, 16 warps ----------------
__global__ __launch_bounds__(NTHR, 1) void mech_kernel(
    const float* __restrict__ x, const float* __restrict__ hid,
    const float* __restrict__ fc1b,
    const float* __restrict__ bih, const float* __restrict__ bhh,
    const float* __restrict__ fc2w, const float* __restrict__ fc2b,
    float* __restrict__ out)
{
    extern __shared__ float sm[];
    float* Gp = sm;                 // [64][264] pair-interleaved: cols 0-127 XA, 128-255 H
    float* PR = sm + OFF_PR;        // [64][264] plain: r | z preacts; later Hnew in 0-127
    float* PN = sm + OFF_PN;        // [64][264] plain: inn | hn preacts (aliases Xp)
    float* Xp = PN;                 // [64][212] pair-interleaved X (dead after fc1)
    int* toks = (int*)(sm + OFF_TOK);
    int* s_tk = toks + TT;

    const int tid = threadIdx.x;
    const int w = tid >> 5, l = tid & 31;
    const int gr = l >> 2, gc = l & 3;
    float* outH = out + (size_t)NTOK * AD;

    int cc[NM], pre[NM]; int total = 0;
    #pragma unroll
    for (int m = 0; m < NM; m++) {
        cc[m] = g_cnt[m];
        total += (cc[m] + TT - 1) / TT;
        pre[m] = total;
    }

    for (;;) {
        if (tid == 0) *s_tk = atomicAdd(&g_ticket, 1);
        __syncthreads();
        const int tk = *s_tk;
        if (tk >= total) break;
        int m = 0;
        #pragma unroll
        for (int j = 0; j < NM - 1; j++) if (tk >= pre[j]) m = j + 1;
        const int prev = m ? pre[m - 1] : 0;
        const int t0 = (tk - prev) * TT;
        const int nt = min(TT, cc[m] - t0);
        if (tid < TT) toks[tid] = g_idx[m * NTOK + t0 + min(tid, nt - 1)];
        __syncthreads();

        // ---- stage X pair-interleaved into Xp ----
        for (int e = tid; e < TT * 52; e += NTHR) {
            int r = e / 52, c4 = e % 52;
            float4 v = make_float4(0.f, 0.f, 0.f, 0.f);
            if (c4 < 51) v = ((const float4*)(x + (size_t)toks[r] * IND))[c4];
            int k0 = c4 * 4;
            float* dst = Xp + r * XPITCH + ((k0 >> 3) << 3) + ((k0 & 7) >> 2);
            dst[0] = v.x; dst[2] = v.y; dst[4] = v.z; dst[6] = v.w;
        }
        // ---- stage H pair-interleaved into Gp cols 128.. ----
        for (int e = tid; e < TT * 32; e += NTHR) {
            int r = e >> 5, c4 = e & 31;
            float4 v = ((const float4*)(hid + (size_t)toks[r] * HD))[c4];
            int k0 = 128 + c4 * 4;
            float* dst = Gp + r * PITCH + ((k0 >> 3) << 3) + ((k0 & 7) >> 2);
            dst[0] = v.x; dst[2] = v.y; dst[4] = v.z; dst[6] = v.w;
        }
        __syncthreads();

        // ---- fc1: 16 warps, warp = m16 x n32 (band = w>>2, ng = w&3) ----
        {
            const int band = w >> 2, ng = w & 3;
            float c[4][4];
            #pragma unroll
            for (int nt_ = 0; nt_ < 4; nt_++) {
                int col = ng * 32 + nt_ * 8 + gc * 2;
                float b0 = __ldg(fc1b + m * HD + col);
                float b1 = __ldg(fc1b + m * HD + col + 1);
                c[nt_][0] = b0; c[nt_][1] = b1;
                c[nt_][2] = b0; c[nt_][3] = b1;
            }
            const uint32_t* Bb = g_bf1 + m * 26624;
            #pragma unroll 2
            for (int kb = 0; kb < 26; kb++) {
                uint32_t a[4];
                {
                    int row = band * 16 + gr;
                    float2 lo = *(const float2*)(Xp + row * XPITCH + kb * 8 + gc * 2);
                    float2 hi = *(const float2*)(Xp + (row + 8) * XPITCH + kb * 8 + gc * 2);
                    a[0] = f2tf(lo.x); a[1] = f2tf(hi.x);
                    a[2] = f2tf(lo.y); a[3] = f2tf(hi.y);
                }
                uint2 b[4];
                #pragma unroll
                for (int nt_ = 0; nt_ < 4; nt_++)
                    b[nt_] = __ldg((const uint2*)(Bb + (kb * 128 + ng * 32 + nt_ * 8 + gr) * 8 + gc * 2));
                #pragma unroll
                for (int nt_ = 0; nt_ < 4; nt_++)
                    mma8(c[nt_], a, b[nt_]);
            }
            // relu + write XA pair-interleaved into Gp cols 0-127
            #pragma unroll
            for (int nt_ = 0; nt_ < 4; nt_++) {
                int row = band * 16 + gr;
                int col = ng * 32 + nt_ * 8 + gc * 2;
                int p = ((col >> 3) << 3) + ((col & 3) << 1) + ((col & 7) >> 2);
                Gp[row * PITCH + p]           = fmaxf(c[nt_][0], 0.f);
                Gp[row * PITCH + p + 2]       = fmaxf(c[nt_][1], 0.f);
                Gp[(row + 8) * PITCH + p]     = fmaxf(c[nt_][2], 0.f);
                Gp[(row + 8) * PITCH + p + 2] = fmaxf(c[nt_][3], 0.f);
            }
        }
        __syncthreads();

        // ---- gates: 16 warps; pair = w>>3 (0: r|z-half r / inn, 1: z / hn),
        //      mb = (w>>2)&1 (m32 stripe), ng = w&3 (n32) ----
        {
            const int pair = w >> 3, mb = (w >> 2) & 1, ng = w & 3;
            // -- r|z: K=256 over Gp concat [XA|H], warp = m32 x n32 --
            {
                float c[2][4][4];
                #pragma unroll
                for (int nt_ = 0; nt_ < 4; nt_++) {
                    int col = ng * 32 + nt_ * 8 + gc * 2;
                    float b0 = __ldg(bih + m * 384 + pair * 128 + col) + __ldg(bhh + m * 384 + pair * 128 + col);
                    float b1 = __ldg(bih + m * 384 + pair * 128 + col + 1) + __ldg(bhh + m * 384 + pair * 128 + col + 1);
                    #pragma unroll
                    for (int mt = 0; mt < 2; mt++) {
                        c[mt][nt_][0] = b0; c[mt][nt_][1] = b1;
                        c[mt][nt_][2] = b0; c[mt][nt_][3] = b1;
                    }
                }
                const uint32_t* Bb = g_brz + m * 65536;
                #pragma unroll 2
                for (int kb = 0; kb < 32; kb++) {
                    uint32_t a[2][4];
                    #pragma unroll
                    for (int mt = 0; mt < 2; mt++) {
                        int row = mb * 32 + mt * 16 + gr;
                        float2 lo = *(const float2*)(Gp + row * PITCH + kb * 8 + gc * 2);
                        float2 hi = *(const float2*)(Gp + (row + 8) * PITCH + kb * 8 + gc * 2);
                        a[mt][0] = f2tf(lo.x); a[mt][1] = f2tf(hi.x);
                        a[mt][2] = f2tf(lo.y); a[mt][3] = f2tf(hi.y);
                    }
                    uint2 b[4];
                    #pragma unroll
                    for (int nt_ = 0; nt_ < 4; nt_++)
                        b[nt_] = __ldg((const uint2*)(Bb + (kb * 256 + pair * 128 + ng * 32 + nt_ * 8 + gr) * 8 + gc * 2));
                    #pragma unroll
                    for (int mt = 0; mt < 2; mt++)
                        #pragma unroll
                        for (int nt_ = 0; nt_ < 4; nt_++)
                            mma8(c[mt][nt_], a[mt], b[nt_]);
                }
                #pragma unroll
                for (int mt = 0; mt < 2; mt++)
                    #pragma unroll
                    for (int nt_ = 0; nt_ < 4; nt_++) {
                        int row = mb * 32 + mt * 16 + gr;
                        int col = pair * 128 + ng * 32 + nt_ * 8 + gc * 2;
                        *(float2*)(PR + row * PITCH + col)       = make_float2(c[mt][nt_][0], c[mt][nt_][1]);
                        *(float2*)(PR + (row + 8) * PITCH + col) = make_float2(c[mt][nt_][2], c[mt][nt_][3]);
                    }
            }
            // -- inn|hn: K=128 (XA half for pair=0, H half for pair=1), warp = m32 x n32 --
            {
                float c[2][4][4];
                #pragma unroll
                for (int nt_ = 0; nt_ < 4; nt_++) {
                    int col = ng * 32 + nt_ * 8 + gc * 2;
                    const float* bsrc = pair ? bhh : bih;
                    float b0 = __ldg(bsrc + m * 384 + 256 + col);
                    float b1 = __ldg(bsrc + m * 384 + 256 + col + 1);
                    #pragma unroll
                    for (int mt = 0; mt < 2; mt++) {
                        c[mt][nt_][0] = b0; c[mt][nt_][1] = b1;
                        c[mt][nt_][2] = b0; c[mt][nt_][3] = b1;
                    }
                }
                const uint32_t* Bb = g_bnq + m * 32768;
                const int kab = pair * 16;
                #pragma unroll 2
                for (int kb = 0; kb < 16; kb++) {
                    uint32_t a[2][4];
                    #pragma unroll
                    for (int mt = 0; mt < 2; mt++) {
                        int row = mb * 32 + mt * 16 + gr;
                        float2 lo = *(const float2*)(Gp + row * PITCH + (kab + kb) * 8 + gc * 2);
                        float2 hi = *(const float2*)(Gp + (row + 8) * PITCH + (kab + kb) * 8 + gc * 2);
                        a[mt][0] = f2tf(lo.x); a[mt][1] = f2tf(hi.x);
                        a[mt][2] = f2tf(lo.y); a[mt][3] = f2tf(hi.y);
                    }
                    uint2 b[4];
                    #pragma unroll
                    for (int nt_ = 0; nt_ < 4; nt_++)
                        b[nt_] = __ldg((const uint2*)(Bb + (kb * 256 + pair * 128 + ng * 32 + nt_ * 8 + gr) * 8 + gc * 2));
                    #pragma unroll
                    for (int mt = 0; mt < 2; mt++)
                        #pragma unroll
                        for (int nt_ = 0; nt_ < 4; nt_++)
                            mma8(c[mt][nt_], a[mt], b[nt_]);
                }
                #pragma unroll
                for (int mt = 0; mt < 2; mt++)
                    #pragma unroll
                    for (int nt_ = 0; nt_ < 4; nt_++) {
                        int row = mb * 32 + mt * 16 + gr;
                        int col = pair * 128 + ng * 32 + nt_ * 8 + gc * 2;
                        *(float2*)(PN + row * PITCH + col)       = make_float2(c[mt][nt_][0], c[mt][nt_][1]);
                        *(float2*)(PN + (row + 8) * PITCH + col) = make_float2(c[mt][nt_][2], c[mt][nt_][3]);
                    }
            }
        }
        __syncthreads();

        // ---- GRU elementwise epilogue ----
        for (int e = tid; e < TT * HD; e += NTHR) {
            int t = e >> 7, o = e & 127;
            float rv = sigmf(PR[t * PITCH + o]);
            float zv = sigmf(PR[t * PITCH + 128 + o]);
            float nv = PN[t * PITCH + o];
            float qv = PN[t * PITCH + 128 + o];
            int ko = 128 + o;
            float hv = Gp[t * PITCH + ((ko >> 3) << 3) + ((ko & 3) << 1) + ((ko & 7) >> 2)];
            float gg = tanhf(nv + rv * qv);
            float hn2 = (1.0f - zv) * gg + zv * hv;
            PR[t * PITCH + o] = hn2;
            outH[(size_t)toks[t] * HD + o] = hn2;
        }
        __syncthreads();

        // ---- fc2 ----
        for (int oi = tid; oi < TT * AD; oi += NTHR) {
            int t = oi / AD, a = oi - t * AD;
            float acc = fc2b[m * AD + a];
            const float* wp = fc2w + m * HD * AD + a;
            const float* hp = PR + t * PITCH;
            #pragma unroll 4
            for (int i = 0; i < HD; i++)
                acc = fmaf(hp[i], __ldg(wp + i * AD), acc);
            out[(size_t)toks[t] * AD + a] = acc;
        }
        // loop-head sync orders next-tile staging after fc2 reads
    }
}

// ---------------- launch ----------------
extern "C" void kernel_launch(void* const* d_in, const int* in_sizes, int n_in,
                              void* d_out, int out_size)
{
    const float* x    = (const float*)d_in[0];
    const float* hid  = (const float*)d_in[1];
    const float* fc1w = (const float*)d_in[2];
    const float* fc1b = (const float*)d_in[3];
    const float* wih  = (const float*)d_in[4];
    const float* whh  = (const float*)d_in[5];
    const float* bih  = (const float*)d_in[6];
    const float* bhh  = (const float*)d_in[7];
    const float* fc2w = (const float*)d_in[8];
    const float* fc2b = (const float*)d_in[9];
    const float* w1   = (const float*)d_in[10];
    const float* b1   = (const float*)d_in[11];
    const float* w2   = (const float*)d_in[12];
    const float* b2   = (const float*)d_in[13];
    const float* w3   = (const float*)d_in[14];
    const float* b3   = (const float*)d_in[15];
    const float* mk   = (const float*)d_in[16];
    const float* wq   = (const float*)d_in[17];
    const float* bq   = (const float*)d_in[18];
    const float* wk   = (const float*)d_in[19];
    const float* bk   = (const float*)d_in[20];
    const float* unif = (const float*)d_in[21];
    float* out = (float*)d_out;

    cudaFuncSetAttribute(mech_kernel, cudaFuncAttributeMaxDynamicSharedMemorySize, SMEM_BYTES);

    kp_kernel<<<1, 128>>>(mk, wk, bk);
    {
        int tot = NBF1 + NBRZ + NBNQ;
        prep_kernel<<<(tot + 255) / 256, 256>>>(fc1w, wih, whh);
    }
    router_kernel<<<NTOK / 64, 256>>>(hid, w1, b1, w2, b2, w3, b3, wq, bq, unif);
    mech_kernel<<<148, NTHR, SMEM_BYTES>>>(x, hid, fc1b, bih, bhh, fc2w, fc2b, out);
}

// round 11
// speedup vs baseline: 2.2426x; 1.0294x over previous
#include <cuda_runtime.h>
#include <math.h>
#include <stdint.h>

#define NTOK 32768
#define NM   4
#define IND  204
#define HD   128
#define AD   14
#define KD   32
#define TT   32
#define NTHR 256
#define FULL 0xffffffffu

#define PITCH   264
#define XPITCH  212
#define HPITCH  132
#define OFF_XP  8448
#define OFF_TOK 15232
#define SMEM_BYTES ((OFF_TOK + 40) * 4)

// ---------------- device scratch ----------------
__device__ float    g_kp[NM * KD];
__device__ int      g_cnt[NM];
__device__ int      g_ticket;
__device__ int      g_idx[NM * NTOK];
// B-fragment-packed tf32 weight images: [kb][n][8] with (k,k+4) pairs adjacent
__device__ __align__(128) uint32_t g_bf1[NM * 26 * 128 * 8];   // fc1: K=208(pad), N=128
__device__ __align__(128) uint32_t g_brz[NM * 32 * 256 * 8];   // r|z: K=256 ([Wi;Wh]), N=256
__device__ __align__(128) uint32_t g_bnq[NM * 16 * 256 * 8];   // inn|hn: K=128, N=256

__device__ __forceinline__ float sigmf(float v) { return 1.0f / (1.0f + __expf(-v)); }
__device__ __forceinline__ uint32_t f2tf(float f) {
    uint32_t r; asm("cvt.rna.tf32.f32 %0,%1;" : "=r"(r) : "f"(f)); return r;
}
__device__ __forceinline__ void mma8(float c[4], const uint32_t a[4], uint2 b) {
    asm volatile("mma.sync.aligned.m16n8k8.row.col.f32.tf32.tf32.f32 "
                 "{%0,%1,%2,%3},{%4,%5,%6,%7},{%8,%9},{%0,%1,%2,%3};"
                 : "+f"(c[0]), "+f"(c[1]), "+f"(c[2]), "+f"(c[3])
                 : "r"(a[0]), "r"(a[1]), "r"(a[2]), "r"(a[3]), "r"(b.x), "r"(b.y));
}
// pair-interleave offset of column k within a row (A-fragment layout)
__device__ __forceinline__ int pil(int k) {
    return ((k >> 3) << 3) + ((k & 3) << 1) + ((k & 7) >> 2);
}

// ---------------- kernel 0: keys + resets ----------------
__global__ void kp_kernel(const float* __restrict__ mech_keys,
                          const float* __restrict__ wk,
                          const float* __restrict__ bk)
{
    int tid = threadIdx.x;
    if (tid == 0) g_ticket = 0;
    if (tid < NM) g_cnt[tid] = 0;
    if (tid < NM * KD) {
        int m = tid >> 5, k = tid & 31;
        float acc = bk[k];
        #pragma unroll
        for (int i = 0; i < KD; i++)
            acc = fmaf(mech_keys[m * KD + i], wk[i * KD + k], acc);
        g_kp[tid] = acc;
    }
}

// ---------------- prep: pack weights into B-fragment tf32 images ----------------
#define NBF1 (NM * 26 * 128 * 8)
#define NBRZ (NM * 32 * 256 * 8)
#define NBNQ (NM * 16 * 256 * 8)
__global__ void prep_kernel(const float* __restrict__ fc1w,
                            const float* __restrict__ wih,
                            const float* __restrict__ whh)
{
    int e = blockIdx.x * blockDim.x + threadIdx.x;
    if (e < NBF1) {
        int m = e / 26624, r = e % 26624;
        int kb = r / 1024, r2 = r % 1024;
        int n = r2 >> 3, p = r2 & 7;
        int k = kb * 8 + (p >> 1) + ((p & 1) << 2);
        float v = (k < IND) ? fc1w[((size_t)m * IND + k) * HD + n] : 0.0f;
        g_bf1[e] = f2tf(v);
    } else if (e < NBF1 + NBRZ) {
        int e2 = e - NBF1;
        int m = e2 / 65536, r = e2 % 65536;
        int kb = r / 2048, r2 = r % 2048;
        int n = r2 >> 3, p = r2 & 7;
        int k = kb * 8 + (p >> 1) + ((p & 1) << 2);
        int gate = n >> 7, col = n & 127;
        float v = (k < 128) ? wih[((size_t)m * HD + k) * 384 + gate * 128 + col]
                            : whh[((size_t)m * HD + (k - 128)) * 384 + gate * 128 + col];
        g_brz[e2] = f2tf(v);
    } else if (e < NBF1 + NBRZ + NBNQ) {
        int e3 = e - NBF1 - NBRZ;
        int m = e3 / 32768, r = e3 % 32768;
        int kb = r / 2048, r2 = r % 2048;
        int n = r2 >> 3, p = r2 & 7;
        int k = kb * 8 + (p >> 1) + ((p & 1) << 2);
        int sel = n >> 7, col = n & 127;
        float v = (sel == 0) ? wih[((size_t)m * HD + k) * 384 + 256 + col]
                             : whh[((size_t)m * HD + k) * 384 + 256 + col];
        g_bnq[e3] = f2tf(v);
    }
}

// ---------------- router (proven fp32 path, unchanged) ----------------
__device__ __forceinline__ void layer32(const float* __restrict__ W,
                                        const float* __restrict__ B,
                                        float cur[8], int l, int do_relu)
{
    float nxt[8];
    #pragma unroll
    for (int t = 0; t < 8; t++) nxt[t] = B[l];
    #pragma unroll 4
    for (int i = 0; i < KD; i++) {
        float wv = W[i * KD + l];
        #pragma unroll
        for (int t = 0; t < 8; t++)
            nxt[t] = fmaf(__shfl_sync(FULL, cur[t], i), wv, nxt[t]);
    }
    #pragma unroll
    for (int t = 0; t < 8; t++)
        cur[t] = do_relu ? fmaxf(nxt[t], 0.0f) : nxt[t];
}

__global__ __launch_bounds__(256) void router_kernel(
    const float* __restrict__ hid,
    const float* __restrict__ w1, const float* __restrict__ b1,
    const float* __restrict__ w2, const float* __restrict__ b2,
    const float* __restrict__ w3, const float* __restrict__ b3,
    const float* __restrict__ wq, const float* __restrict__ bq,
    const float* __restrict__ unif)
{
    __shared__ float hs[64 * HD];
    const int tid = threadIdx.x;
    const int t0 = blockIdx.x * 64;
    {
        const float4* src = (const float4*)(hid + (size_t)t0 * HD);
        float4* dst = (float4*)hs;
        for (int e = tid; e < 64 * HD / 4; e += 256) dst[e] = src[e];
    }
    __syncthreads();
    const int w = tid >> 5, l = tid & 31;
    const int wt0 = w * 8;
    float cur[8];
    #pragma unroll
    for (int t = 0; t < 8; t++) cur[t] = b1[l];
    #pragma unroll 4
    for (int i = 0; i < HD; i++) {
        float wv = w1[i * KD + l];
        #pragma unroll
        for (int t = 0; t < 8; t++)
            cur[t] = fmaf(hs[(wt0 + t) * HD + i], wv, cur[t]);
    }
    #pragma unroll
    for (int t = 0; t < 8; t++) cur[t] = fmaxf(cur[t], 0.0f);
    layer32(w2, b2, cur, l, 1);
    layer32(w3, b3, cur, l, 0);
    layer32(wq, bq, cur, l, 0);

    const float scale = 0.17677669529663687f;
    int mysel = 0;
    int mytok = t0 + wt0 + l;
    #pragma unroll
    for (int t = 0; t < 8; t++) {
        float lg[NM];
        #pragma unroll
        for (int m = 0; m < NM; m++) {
            float p = cur[t] * g_kp[m * KD + l];
            #pragma unroll
            for (int off = 16; off > 0; off >>= 1)
                p += __shfl_xor_sync(FULL, p, off);
            lg[m] = p * scale;
        }
        float mx = fmaxf(fmaxf(lg[0], lg[1]), fmaxf(lg[2], lg[3]));
        float es[NM]; float ssum = 0.0f;
        #pragma unroll
        for (int m = 0; m < NM; m++) { es[m] = expf(lg[m] - mx); ssum += es[m]; }
        float inv = 1.0f / ssum;
        int gt = t0 + wt0 + t;
        float best = -1e30f; int sel = 0;
        #pragma unroll
        for (int m = 0; m < NM; m++) {
            float u = unif[gt * NM + m];
            float gmb = -logf(-logf(u + 1e-10f) + 1e-10f);
            float y = es[m] * inv + gmb;
            if (y > best) { best = y; sel = m; }
        }
        if (l == t) mysel = sel;
    }
    #pragma unroll
    for (int m = 0; m < NM; m++) {
        unsigned mask = __ballot_sync(FULL, (l < 8) && (mysel == m));
        if (mask) {
            int leader = __ffs(mask) - 1;
            int base = 0;
            if (l == leader) base = atomicAdd(&g_cnt[m], __popc(mask));
            base = __shfl_sync(FULL, base, leader);
            if ((l < 8) && (mysel == m)) {
                int pos = base + __popc(mask & ((1u << l) - 1));
                g_idx[m * NTOK + pos] = mytok;
            }
        }
    }
}

// ---------------- mech: persistent mma.sync-tf32 fused GRU agent, 2 blocks/SM ----------------
__global__ __launch_bounds__(NTHR, 2) void mech_kernel(
    const float* __restrict__ x, const float* __restrict__ hid,
    const float* __restrict__ fc1b,
    const float* __restrict__ bih, const float* __restrict__ bhh,
    const float* __restrict__ fc2w, const float* __restrict__ fc2b,
    float* __restrict__ out)
{
    extern __shared__ float sm[];
    float* Gp = sm;                 // [32][264] pair-interleaved: cols 0-127 XA, 128-255 H
    float* Xp = sm + OFF_XP;        // [32][212] pair-interleaved X (dead after fc1)
    float* HN = Xp;                 // [32][132] plain hnew (aliases Xp)
    int* toks = (int*)(sm + OFF_TOK);
    int* s_tk = toks + TT;

    const int tid = threadIdx.x;
    const int w = tid >> 5, l = tid & 31;
    const int gr = l >> 2, gc = l & 3;
    const int mb = w >> 2, ng = w & 3;     // warp: m16-stripe, n32-group
    float* outH = out + (size_t)NTOK * AD;

    int cc[NM], pre[NM]; int total = 0;
    #pragma unroll
    for (int m = 0; m < NM; m++) {
        cc[m] = g_cnt[m];
        total += (cc[m] + TT - 1) / TT;
        pre[m] = total;
    }

    for (;;) {
        if (tid == 0) *s_tk = atomicAdd(&g_ticket, 1);
        __syncthreads();
        const int tk = *s_tk;
        if (tk >= total) break;
        int m = 0;
        #pragma unroll
        for (int j = 0; j < NM - 1; j++) if (tk >= pre[j]) m = j + 1;
        const int prev = m ? pre[m - 1] : 0;
        const int t0 = (tk - prev) * TT;
        const int nt_tok = min(TT, cc[m] - t0);
        if (tid < TT) toks[tid] = g_idx[m * NTOK + t0 + min(tid, nt_tok - 1)];
        __syncthreads();

        // ---- stage X pair-interleaved into Xp ----
        for (int e = tid; e < TT * 52; e += NTHR) {
            int r = e / 52, c4 = e % 52;
            float4 v = make_float4(0.f, 0.f, 0.f, 0.f);
            if (c4 < 51) v = ((const float4*)(x + (size_t)toks[r] * IND))[c4];
            int k0 = c4 * 4;
            float* dst = Xp + r * XPITCH + ((k0 >> 3) << 3) + ((k0 & 7) >> 2);
            dst[0] = v.x; dst[2] = v.y; dst[4] = v.z; dst[6] = v.w;
        }
        // ---- stage H pair-interleaved into Gp cols 128.. ----
        for (int e = tid; e < TT * 32; e += NTHR) {
            int r = e >> 5, c4 = e & 31;
            float4 v = ((const float4*)(hid + (size_t)toks[r] * HD))[c4];
            int k0 = 128 + c4 * 4;
            float* dst = Gp + r * PITCH + ((k0 >> 3) << 3) + ((k0 & 7) >> 2);
            dst[0] = v.x; dst[2] = v.y; dst[4] = v.z; dst[6] = v.w;
        }
        __syncthreads();

        // ---- fc1: 8 warps, warp = m16 x n32 (band = mb, ng) ----
        {
            float c[4][4];
            #pragma unroll
            for (int nt = 0; nt < 4; nt++) {
                int col = ng * 32 + nt * 8 + gc * 2;
                float b0 = __ldg(fc1b + m * HD + col);
                float b1 = __ldg(fc1b + m * HD + col + 1);
                c[nt][0] = b0; c[nt][1] = b1;
                c[nt][2] = b0; c[nt][3] = b1;
            }
            const uint32_t* Bb = g_bf1 + m * 26624;
            #pragma unroll 2
            for (int kb = 0; kb < 26; kb++) {
                uint32_t a[4];
                {
                    int row = mb * 16 + gr;
                    float2 lo = *(const float2*)(Xp + row * XPITCH + kb * 8 + gc * 2);
                    float2 hi = *(const float2*)(Xp + (row + 8) * XPITCH + kb * 8 + gc * 2);
                    a[0] = f2tf(lo.x); a[1] = f2tf(hi.x);
                    a[2] = f2tf(lo.y); a[3] = f2tf(hi.y);
                }
                #pragma unroll
                for (int nt = 0; nt < 4; nt++) {
                    uint2 b = __ldg((const uint2*)(Bb + ((size_t)kb * 128 + ng * 32 + nt * 8 + gr) * 8 + gc * 2));
                    mma8(c[nt], a, b);
                }
            }
            // relu + write XA pair-interleaved into Gp cols 0-127
            #pragma unroll
            for (int nt = 0; nt < 4; nt++) {
                int row = mb * 16 + gr;
                int col = ng * 32 + nt * 8 + gc * 2;
                int p = pil(col);
                Gp[row * PITCH + p]           = fmaxf(c[nt][0], 0.f);
                Gp[row * PITCH + p + 2]       = fmaxf(c[nt][1], 0.f);
                Gp[(row + 8) * PITCH + p]     = fmaxf(c[nt][2], 0.f);
                Gp[(row + 8) * PITCH + p + 2] = fmaxf(c[nt][3], 0.f);
            }
        }
        __syncthreads();

        // ---- gates + in-register GRU epilogue: warp = m16 x n32 slab of h' ----
        {
            const int rowb = mb * 16;
            const uint32_t* Brz = g_brz + m * 65536;
            const uint32_t* Bnq = g_bnq + m * 32768;
            float cr[4][4], cz[4][4], cn[4][4], cq[4][4];
            #pragma unroll
            for (int nt = 0; nt < 4; nt++) {
                int col = ng * 32 + nt * 8 + gc * 2;
                float r0 = __ldg(bih + m * 384 + col) + __ldg(bhh + m * 384 + col);
                float r1 = __ldg(bih + m * 384 + col + 1) + __ldg(bhh + m * 384 + col + 1);
                float z0 = __ldg(bih + m * 384 + 128 + col) + __ldg(bhh + m * 384 + 128 + col);
                float z1 = __ldg(bih + m * 384 + 128 + col + 1) + __ldg(bhh + m * 384 + 128 + col + 1);
                float n0 = __ldg(bih + m * 384 + 256 + col);
                float n1 = __ldg(bih + m * 384 + 256 + col + 1);
                float q0 = __ldg(bhh + m * 384 + 256 + col);
                float q1 = __ldg(bhh + m * 384 + 256 + col + 1);
                cr[nt][0] = r0; cr[nt][1] = r1; cr[nt][2] = r0; cr[nt][3] = r1;
                cz[nt][0] = z0; cz[nt][1] = z1; cz[nt][2] = z0; cz[nt][3] = z1;
                cn[nt][0] = n0; cn[nt][1] = n1; cn[nt][2] = n0; cn[nt][3] = n1;
                cq[nt][0] = q0; cq[nt][1] = q1; cq[nt][2] = q0; cq[nt][3] = q1;
            }
            // r and z share the K=256 A-pass over [XA|H]
            #pragma unroll 2
            for (int kb = 0; kb < 32; kb++) {
                uint32_t a[4];
                float2 lo = *(const float2*)(Gp + (rowb + gr) * PITCH + kb * 8 + gc * 2);
                float2 hi = *(const float2*)(Gp + (rowb + gr + 8) * PITCH + kb * 8 + gc * 2);
                a[0] = f2tf(lo.x); a[1] = f2tf(hi.x);
                a[2] = f2tf(lo.y); a[3] = f2tf(hi.y);
                #pragma unroll
                for (int nt = 0; nt < 4; nt++) {
                    uint2 br = __ldg((const uint2*)(Brz + ((size_t)kb * 256 + ng * 32 + nt * 8 + gr) * 8 + gc * 2));
                    uint2 bz = __ldg((const uint2*)(Brz + ((size_t)kb * 256 + 128 + ng * 32 + nt * 8 + gr) * 8 + gc * 2));
                    mma8(cr[nt], a, br);
                    mma8(cz[nt], a, bz);
                }
            }
            // inn: A kb 0..15 (XA half), B rows 0..127 of g_bnq
            #pragma unroll 2
            for (int kb = 0; kb < 16; kb++) {
                uint32_t a[4];
                float2 lo = *(const float2*)(Gp + (rowb + gr) * PITCH + kb * 8 + gc * 2);
                float2 hi = *(const float2*)(Gp + (rowb + gr + 8) * PITCH + kb * 8 + gc * 2);
                a[0] = f2tf(lo.x); a[1] = f2tf(hi.x);
                a[2] = f2tf(lo.y); a[3] = f2tf(hi.y);
                #pragma unroll
                for (int nt = 0; nt < 4; nt++) {
                    uint2 b = __ldg((const uint2*)(Bnq + ((size_t)kb * 256 + ng * 32 + nt * 8 + gr) * 8 + gc * 2));
                    mma8(cn[nt], a, b);
                }
            }
            // hn: A kb 16..31 (H half), B rows 128..255 of g_bnq (image kb 0..15)
            #pragma unroll 2
            for (int kb = 16; kb < 32; kb++) {
                uint32_t a[4];
                float2 lo = *(const float2*)(Gp + (rowb + gr) * PITCH + kb * 8 + gc * 2);
                float2 hi = *(const float2*)(Gp + (rowb + gr + 8) * PITCH + kb * 8 + gc * 2);
                a[0] = f2tf(lo.x); a[1] = f2tf(hi.x);
                a[2] = f2tf(lo.y); a[3] = f2tf(hi.y);
                #pragma unroll
                for (int nt = 0; nt < 4; nt++) {
                    uint2 b = __ldg((const uint2*)(Bnq + ((size_t)(kb - 16) * 256 + 128 + ng * 32 + nt * 8 + gr) * 8 + gc * 2));
                    mma8(cq[nt], a, b);
                }
            }
            // in-register GRU epilogue
            #pragma unroll
            for (int nt = 0; nt < 4; nt++) {
                int colb = ng * 32 + nt * 8 + gc * 2;
                #pragma unroll
                for (int idx = 0; idx < 4; idx++) {
                    int row = rowb + gr + ((idx >> 1) << 3);
                    int col = colb + (idx & 1);
                    float rv = sigmf(cr[nt][idx]);
                    float zv = sigmf(cz[nt][idx]);
                    float gg = tanhf(cn[nt][idx] + rv * cq[nt][idx]);
                    float hv = Gp[row * PITCH + pil(128 + col)];
                    float h2 = (1.0f - zv) * gg + zv * hv;
                    HN[row * HPITCH + col] = h2;
                    outH[(size_t)toks[row] * HD + col] = h2;
                }
            }
        }
        __syncthreads();

        // ---- fc2 over hnew (HN plain) ----
        for (int oi = tid; oi < TT * AD; oi += NTHR) {
            int t = oi / AD, a = oi - t * AD;
            float acc = fc2b[m * AD + a];
            const float* wp = fc2w + m * HD * AD + a;
            const float* hp = HN + t * HPITCH;
            #pragma unroll 4
            for (int i = 0; i < HD; i++)
                acc = fmaf(hp[i], __ldg(wp + i * AD), acc);
            out[(size_t)toks[t] * AD + a] = acc;
        }
        // loop-head sync orders next-tile staging after fc2 reads
    }
}

// ---------------- launch ----------------
extern "C" void kernel_launch(void* const* d_in, const int* in_sizes, int n_in,
                              void* d_out, int out_size)
{
    const float* x    = (const float*)d_in[0];
    const float* hid  = (const float*)d_in[1];
    const float* fc1w = (const float*)d_in[2];
    const float* fc1b = (const float*)d_in[3];
    const float* wih  = (const float*)d_in[4];
    const float* whh  = (const float*)d_in[5];
    const float* bih  = (const float*)d_in[6];
    const float* bhh  = (const float*)d_in[7];
    const float* fc2w = (const float*)d_in[8];
    const float* fc2b = (const float*)d_in[9];
    const float* w1   = (const float*)d_in[10];
    const float* b1   = (const float*)d_in[11];
    const float* w2   = (const float*)d_in[12];
    const float* b2   = (const float*)d_in[13];
    const float* w3   = (const float*)d_in[14];
    const float* b3   = (const float*)d_in[15];
    const float* mk   = (const float*)d_in[16];
    const float* wq   = (const float*)d_in[17];
    const float* bq   = (const float*)d_in[18];
    const float* wk   = (const float*)d_in[19];
    const float* bk   = (const float*)d_in[20];
    const float* unif = (const float*)d_in[21];
    float* out = (float*)d_out;

    cudaFuncSetAttribute(mech_kernel, cudaFuncAttributeMaxDynamicSharedMemorySize, SMEM_BYTES);

    kp_kernel<<<1, 128>>>(mk, wk, bk);
    {
        int tot = NBF1 + NBRZ + NBNQ;
        prep_kernel<<<(tot + 255) / 256, 256>>>(fc1w, wih, whh);
    }
    router_kernel<<<NTOK / 64, 256>>>(hid, w1, b1, w2, b2, w3, b3, wq, bq, unif);
    mech_kernel<<<296, NTHR, SMEM_BYTES>>>(x, hid, fc1b, bih, bhh, fc2w, fc2b, out);
}